// round 14
// baseline (speedup 1.0000x reference)
#include <cuda_runtime.h>
#include <cuda_bf16.h>
#include <cuda_fp16.h>
#include <mma.h>
#include <math.h>
#include <stdint.h>

using namespace nvcuda;

// Problem constants
#define BB 2
#define SS 2048
#define HH 2048
#define NHEAD 16
#define HDIM 128
#define H3 6144
#define VP 320
#define MALL 4096

// -------- fp32 scratch --------
__device__ float g_qkv[BB * SS * H3];

// -------- fp16 operands --------
__device__ __half g_x16 [MALL * HH];                      // x single
__device__ __half g_wq16[H3 * HH];
__device__ __half g_wd16[HH * HH];
__device__ __half g_ah16[MALL * HH], g_al16[MALL * HH];   // flash output att hi/lo
__device__ __half g_qh16[MALL * HH], g_ql16[MALL * HH];   // roped q hi/lo
__device__ __half g_k16 [MALL * HH];                      // roped k single
__device__ __half g_v16 [MALL * HH];                      // restored v single

// -------- bf16 hi/lo scratch (V bottleneck path) --------
__device__ __nv_bfloat16 g_vh [MALL * HH],  g_vl [MALL * HH];
__device__ __nv_bfloat16 g_wch[VP * HH],    g_wcl[VP * HH];
__device__ __nv_bfloat16 g_vch[MALL * VP],  g_vcl[MALL * VP];
__device__ __nv_bfloat16 g_wrh[HH * VP],    g_wrl[HH * VP];

// ============================================================================
// helpers
// ============================================================================
__device__ __forceinline__ uint32_t smem_u32(const void* p) {
    uint32_t a;
    asm("{ .reg .u64 t; cvta.to.shared.u64 t, %1; cvt.u32.u64 %0, t; }"
        : "=r"(a) : "l"(p));
    return a;
}
__device__ __forceinline__ void cp16(uint32_t s, const void* g, uint32_t nbytes) {
    asm volatile("cp.async.cg.shared.global [%0], [%1], 16, %2;"
                 :: "r"(s), "l"(g), "r"(nbytes) : "memory");
}
__device__ __forceinline__ void cp_commit() {
    asm volatile("cp.async.commit_group;" ::: "memory");
}
template <int N>
__device__ __forceinline__ void cp_wait() {
    asm volatile("cp.async.wait_group %0;" :: "n"(N) : "memory");
}
__device__ __forceinline__ void split1(float v, __nv_bfloat16& h, __nv_bfloat16& l) {
    h = __float2bfloat16(v);
    l = __float2bfloat16(v - __bfloat162float(h));
}
__device__ __forceinline__ void split1h(float v, __half& h, __half& l) {
    h = __float2half(v);
    l = __float2half(v - __half2float(h));
}
__device__ __forceinline__ uint32_t pack2(__nv_bfloat16 a, __nv_bfloat16 b) {
    return (uint32_t)__bfloat16_as_ushort(a) |
           ((uint32_t)__bfloat16_as_ushort(b) << 16);
}
__device__ __forceinline__ uint32_t pack2h(__half a, __half b) {
    return (uint32_t)__half_as_ushort(a) |
           ((uint32_t)__half_as_ushort(b) << 16);
}

// ============================================================================
// conversion kernels
// ============================================================================
__global__ void split_kernel(const float* __restrict__ src,
                             __nv_bfloat16* __restrict__ hi,
                             __nv_bfloat16* __restrict__ lo, int n)
{
    int i = (blockIdx.x * blockDim.x + threadIdx.x) * 4;
    if (i >= n) return;
    float4 v = *(const float4*)(src + i);
    __nv_bfloat16 h0, h1, h2, h3, l0, l1, l2, l3;
    split1(v.x, h0, l0); split1(v.y, h1, l1);
    split1(v.z, h2, l2); split1(v.w, h3, l3);
    *(uint2*)(hi + i) = make_uint2(pack2(h0, h1), pack2(h2, h3));
    *(uint2*)(lo + i) = make_uint2(pack2(l0, l1), pack2(l2, l3));
}

__global__ void conv_f16_kernel(const float* __restrict__ src,
                                __half* __restrict__ dst, int n)
{
    int i = (blockIdx.x * blockDim.x + threadIdx.x) * 4;
    if (i >= n) return;
    float4 v = *(const float4*)(src + i);
    *(uint2*)(dst + i) = make_uint2(pack2h(__float2half(v.x), __float2half(v.y)),
                                    pack2h(__float2half(v.z), __float2half(v.w)));
}

// v slice of g_qkv -> contiguous bf16 hi/lo [MALL x HH]
__global__ void split_v_kernel()
{
    int i = (blockIdx.x * blockDim.x + threadIdx.x) * 4;
    if (i >= MALL * HH) return;
    int r = i / HH, c = i % HH;
    float4 v = *(const float4*)(g_qkv + (size_t)r * H3 + 2 * HH + c);
    __nv_bfloat16 h0, h1, h2, h3, l0, l1, l2, l3;
    split1(v.x, h0, l0); split1(v.y, h1, l1);
    split1(v.z, h2, l2); split1(v.w, h3, l3);
    *(uint2*)(g_vh + i) = make_uint2(pack2(h0, h1), pack2(h2, h3));
    *(uint2*)(g_vl + i) = make_uint2(pack2(l0, l1), pack2(l2, l3));
}

// ============================================================================
// fused RoPE + convert: q -> fp16 hi/lo, k -> fp16 single
// ============================================================================
__global__ void rope_split_kernel()
{
    const int gw   = blockIdx.x * 8 + (threadIdx.x >> 5);
    const int lane = threadIdx.x & 31;
    const int h = gw & 15;
    const int s = (gw >> 4) & 2047;
    const int b = gw >> 15;

    const size_t qbase = (size_t)(b * SS + s) * H3 + h * HDIM;
    const int d0 = lane * 4;
    float4 q = *(const float4*)(g_qkv + qbase + d0);
    float4 k = *(const float4*)(g_qkv + qbase + HH + d0);

    float4 qp, kp;
    qp.x = __shfl_xor_sync(0xffffffffu, q.x, 4);
    qp.y = __shfl_xor_sync(0xffffffffu, q.y, 4);
    qp.z = __shfl_xor_sync(0xffffffffu, q.z, 4);
    qp.w = __shfl_xor_sync(0xffffffffu, q.w, 4);
    kp.x = __shfl_xor_sync(0xffffffffu, k.x, 4);
    kp.y = __shfl_xor_sync(0xffffffffu, k.y, 4);
    kp.z = __shfl_xor_sync(0xffffffffu, k.z, 4);
    kp.w = __shfl_xor_sync(0xffffffffu, k.w, 4);

    if (lane < 8) {
        const float sgn = (lane < 4) ? -1.0f : 1.0f;
        float qa[4] = {q.x, q.y, q.z, q.w};
        float pa[4] = {qp.x, qp.y, qp.z, qp.w};
        float ka[4] = {k.x, k.y, k.z, k.w};
        float kb[4] = {kp.x, kp.y, kp.z, kp.w};
#pragma unroll
        for (int i = 0; i < 4; i++) {
            int j = (lane & 3) * 4 + i;
            float inv = __expf(-(float)(2 * j) * (9.210340371976184f / 32.0f));
            float sn, cs;
            sincosf((float)s * inv, &sn, &cs);
            qa[i] = qa[i] * cs + sgn * pa[i] * sn;
            ka[i] = ka[i] * cs + sgn * kb[i] * sn;
        }
        q = make_float4(qa[0], qa[1], qa[2], qa[3]);
        k = make_float4(ka[0], ka[1], ka[2], ka[3]);
    }

    const size_t o = (size_t)(b * SS + s) * HH + h * HDIM + d0;
    __half h0, h1, h2, h3, l0, l1, l2, l3;
    split1h(q.x, h0, l0); split1h(q.y, h1, l1);
    split1h(q.z, h2, l2); split1h(q.w, h3, l3);
    *(uint2*)(g_qh16 + o) = make_uint2(pack2h(h0, h1), pack2h(h2, h3));
    *(uint2*)(g_ql16 + o) = make_uint2(pack2h(l0, l1), pack2h(l2, l3));
    *(uint2*)(g_k16 + o)  = make_uint2(pack2h(__float2half(k.x), __float2half(k.y)),
                                       pack2h(__float2half(k.z), __float2half(k.w)));
}

// ============================================================================
// fp16 GEMM, NA = number of A terms (1: single-pass; 2: A = Ah + Al).
// C = A @ B^T + bias, fp32 out. 128x256 CTA, 512 thr (2x8 warps), warp 64x32.
// ============================================================================
#define PADH     40
#define A_TILE_H (128 * PADH * 2)
#define B_TILE_H (256 * PADH * 2)

template <int NA>
__global__ __launch_bounds__(512, 1) void gemm_f16_kernel(
    const __half* __restrict__ Ah, const __half* __restrict__ Al,
    const __half* __restrict__ Bw,
    const float* __restrict__ bias, float* __restrict__ C,
    int ldc, int N, int K)
{
    constexpr int STAGE = NA * A_TILE_H + B_TILE_H;

    extern __shared__ char smem[];
    const uint32_t sbase = smem_u32(smem);
    const int t    = threadIdx.x;
    const int w    = t >> 5;
    const int lane = t & 31;
    const int wm   = w >> 3;
    const int wn   = w & 7;
    const int m0   = blockIdx.y * 128;
    const int n0   = blockIdx.x * 256;

    wmma::fragment<wmma::accumulator, 16, 16, 16, float> acc[4][2];
#pragma unroll
    for (int i = 0; i < 4; i++)
#pragma unroll
        for (int j = 0; j < 2; j++) wmma::fill_fragment(acc[i][j], 0.0f);

    const int nchunks = K / 32;

    auto load_stage = [&](int chunk, int stage) {
        const int kk = chunk * 32;
        const uint32_t sst = sbase + stage * STAGE;
#pragma unroll
        for (int rep = 0; rep < NA; rep++) {
            const int v = t + rep * 512;
            const int tile = v >> 9;
            const int r = (v >> 2) & 127;
            const int c = (v & 3) * 8;
            const __half* src = tile ? Al : Ah;
            cp16(sst + tile * A_TILE_H + r * (PADH * 2) + c * 2,
                 src + (size_t)(m0 + r) * K + kk + c, 16);
        }
#pragma unroll
        for (int rep = 0; rep < 2; rep++) {
            const int v = t + rep * 512;
            const int r = v >> 2;
            const int c = (v & 3) * 8;
            const int brow = n0 + r;
            const uint32_t vb = (brow < N) ? 16u : 0u;
            cp16(sst + NA * A_TILE_H + r * (PADH * 2) + c * 2,
                 Bw + (size_t)(brow < N ? brow : 0) * K + kk + c, vb);
        }
        cp_commit();
    };

    load_stage(0, 0);

    for (int chunk = 0; chunk < nchunks; chunk++) {
        const int stage = chunk & 1;
        if (chunk + 1 < nchunks) { load_stage(chunk + 1, stage ^ 1); cp_wait<1>(); }
        else cp_wait<0>();
        __syncthreads();

        const __half* sAh = (const __half*)(smem + stage * STAGE);
        const __half* sAl = (const __half*)(smem + stage * STAGE + A_TILE_H);
        const __half* sB  = (const __half*)(smem + stage * STAGE + NA * A_TILE_H);

#pragma unroll
        for (int ks = 0; ks < 2; ks++) {
            wmma::fragment<wmma::matrix_b, 16, 16, 16, __half, wmma::col_major> bf[2];
#pragma unroll
            for (int j = 0; j < 2; j++) {
                const int col = wn * 32 + j * 16;
                wmma::load_matrix_sync(bf[j], sB + col * PADH + ks * 16, PADH);
            }
#pragma unroll
            for (int i = 0; i < 4; i++) {
                const int row = wm * 64 + i * 16;
                wmma::fragment<wmma::matrix_a, 16, 16, 16, __half, wmma::row_major> ah;
                wmma::load_matrix_sync(ah, sAh + row * PADH + ks * 16, PADH);
#pragma unroll
                for (int j = 0; j < 2; j++)
                    wmma::mma_sync(acc[i][j], ah, bf[j], acc[i][j]);
                if (NA == 2) {
                    wmma::fragment<wmma::matrix_a, 16, 16, 16, __half, wmma::row_major> al;
                    wmma::load_matrix_sync(al, sAl + row * PADH + ks * 16, PADH);
#pragma unroll
                    for (int j = 0; j < 2; j++)
                        wmma::mma_sync(acc[i][j], al, bf[j], acc[i][j]);
                }
            }
        }
        __syncthreads();
    }

    float* epi = (float*)(smem) + w * 256;
#pragma unroll
    for (int i = 0; i < 4; i++)
#pragma unroll
        for (int j = 0; j < 2; j++) {
            const int gcol0 = n0 + wn * 32 + j * 16;
            if (gcol0 < N) {
                wmma::store_matrix_sync(epi, acc[i][j], 16, wmma::mem_row_major);
                __syncwarp();
                const int row  = lane >> 1;
                const int coff = (lane & 1) * 8;
                const int grow = m0 + wm * 64 + i * 16 + row;
                const int gcol = gcol0 + coff;
                float4 b0 = *(const float4*)(bias + gcol);
                float4 b1 = *(const float4*)(bias + gcol + 4);
                const float* e = epi + row * 16 + coff;
                float* cp = C + (size_t)grow * ldc + gcol;
                *(float4*)cp       = make_float4(e[0] + b0.x, e[1] + b0.y,
                                                 e[2] + b0.z, e[3] + b0.w);
                *(float4*)(cp + 4) = make_float4(e[4] + b1.x, e[5] + b1.y,
                                                 e[6] + b1.z, e[7] + b1.w);
                __syncwarp();
            }
        }
}

#define GEMM16_SMEM_1 (2 * (1 * A_TILE_H + B_TILE_H))   // 61440
#define GEMM16_SMEM_2 (2 * (2 * A_TILE_H + B_TILE_H))   // 81920

// ============================================================================
// 3-term bf16 GEMM (Vc, Vr). Output modes: fp32 C / bf16 hi-lo / fp16 single.
// ============================================================================
#define PADE    40
#define A_TILE  (128 * PADE * 2)

template <int WN>
__global__ __launch_bounds__(512, 1) void gemm_wmma_kernel(
    const __nv_bfloat16* __restrict__ Ah, const __nv_bfloat16* __restrict__ Al,
    const __nv_bfloat16* __restrict__ Bh, const __nv_bfloat16* __restrict__ Bl,
    const float* __restrict__ bias,
    float* __restrict__ C,
    __nv_bfloat16* __restrict__ Chi, __nv_bfloat16* __restrict__ Clo,
    __half* __restrict__ Ch16,
    int ldc, int N, int K)
{
    constexpr int BN      = WN * 8;
    constexpr int B_TILE  = BN * PADE * 2;
    constexpr int STAGE   = 2 * A_TILE + 2 * B_TILE;
    constexpr int NJ      = WN / 16;

    extern __shared__ char smem[];
    const uint32_t sbase = smem_u32(smem);
    const int t    = threadIdx.x;
    const int w    = t >> 5;
    const int lane = t & 31;
    const int wm   = w >> 3;
    const int wn   = w & 7;
    const int m0   = blockIdx.y * 128;
    const int n0   = blockIdx.x * BN;

    wmma::fragment<wmma::accumulator, 16, 16, 16, float> acc[4][NJ];
#pragma unroll
    for (int i = 0; i < 4; i++)
#pragma unroll
        for (int j = 0; j < NJ; j++) wmma::fill_fragment(acc[i][j], 0.0f);

    const int nchunks = K / 32;

    auto load_stage = [&](int chunk, int stage) {
        const int kk = chunk * 32;
        const uint32_t sst = sbase + stage * STAGE;
#pragma unroll
        for (int rep = 0; rep < 2; rep++) {
            const int v = t + rep * 512;
            const int tile = v >> 9;
            const int r = (v >> 2) & 127;
            const int c = (v & 3) * 8;
            const __nv_bfloat16* src = tile ? Al : Ah;
            cp16(sst + tile * A_TILE + r * (PADE * 2) + c * 2,
                 src + (size_t)(m0 + r) * K + kk + c, 16);
        }
        constexpr int BREP = (BN * 8) / 512;
#pragma unroll
        for (int rep = 0; rep < BREP; rep++) {
            const int v = t + rep * 512;
            const int tile = v / (BN * 4);
            const int r = (v >> 2) % BN;
            const int c = (v & 3) * 8;
            const __nv_bfloat16* src = tile ? Bl : Bh;
            const int brow = n0 + r;
            const uint32_t vb = (brow < N) ? 16u : 0u;
            cp16(sst + 2 * A_TILE + tile * B_TILE + r * (PADE * 2) + c * 2,
                 src + (size_t)(brow < N ? brow : 0) * K + kk + c, vb);
        }
        cp_commit();
    };

    load_stage(0, 0);

    for (int chunk = 0; chunk < nchunks; chunk++) {
        const int stage = chunk & 1;
        if (chunk + 1 < nchunks) { load_stage(chunk + 1, stage ^ 1); cp_wait<1>(); }
        else cp_wait<0>();
        __syncthreads();

        const __nv_bfloat16* sAh = (const __nv_bfloat16*)(smem + stage * STAGE);
        const __nv_bfloat16* sAl = (const __nv_bfloat16*)(smem + stage * STAGE + A_TILE);
        const __nv_bfloat16* sBh = (const __nv_bfloat16*)(smem + stage * STAGE + 2 * A_TILE);
        const __nv_bfloat16* sBl = (const __nv_bfloat16*)(smem + stage * STAGE + 2 * A_TILE + B_TILE);

#pragma unroll
        for (int ks = 0; ks < 2; ks++) {
            wmma::fragment<wmma::matrix_b, 16, 16, 16, __nv_bfloat16, wmma::col_major> bh[NJ], bl[NJ];
#pragma unroll
            for (int j = 0; j < NJ; j++) {
                const int col = wn * WN + j * 16;
                wmma::load_matrix_sync(bh[j], sBh + col * PADE + ks * 16, PADE);
                wmma::load_matrix_sync(bl[j], sBl + col * PADE + ks * 16, PADE);
            }
#pragma unroll
            for (int i = 0; i < 4; i++) {
                const int row = wm * 64 + i * 16;
                wmma::fragment<wmma::matrix_a, 16, 16, 16, __nv_bfloat16, wmma::row_major> ah, al;
                wmma::load_matrix_sync(ah, sAh + row * PADE + ks * 16, PADE);
                wmma::load_matrix_sync(al, sAl + row * PADE + ks * 16, PADE);
#pragma unroll
                for (int j = 0; j < NJ; j++) {
                    wmma::mma_sync(acc[i][j], ah, bh[j], acc[i][j]);
                    wmma::mma_sync(acc[i][j], ah, bl[j], acc[i][j]);
                    wmma::mma_sync(acc[i][j], al, bh[j], acc[i][j]);
                }
            }
        }
        __syncthreads();
    }

    float* epi = (float*)(smem) + w * 256;
#pragma unroll
    for (int i = 0; i < 4; i++)
#pragma unroll
        for (int j = 0; j < NJ; j++) {
            const int gcol0 = n0 + wn * WN + j * 16;
            if (gcol0 < N) {
                wmma::store_matrix_sync(epi, acc[i][j], 16, wmma::mem_row_major);
                __syncwarp();
                const int row  = lane >> 1;
                const int coff = (lane & 1) * 8;
                const int grow = m0 + wm * 64 + i * 16 + row;
                const int gcol = gcol0 + coff;
                float4 b0 = *(const float4*)(bias + gcol);
                float4 b1 = *(const float4*)(bias + gcol + 4);
                const float* e = epi + row * 16 + coff;
                float vals[8] = {e[0] + b0.x, e[1] + b0.y, e[2] + b0.z, e[3] + b0.w,
                                 e[4] + b1.x, e[5] + b1.y, e[6] + b1.z, e[7] + b1.w};
                if (C != nullptr) {
                    float* cp = C + (size_t)grow * ldc + gcol;
                    *(float4*)cp       = make_float4(vals[0], vals[1], vals[2], vals[3]);
                    *(float4*)(cp + 4) = make_float4(vals[4], vals[5], vals[6], vals[7]);
                } else if (Chi != nullptr) {
                    __nv_bfloat16 hh[8], ll[8];
#pragma unroll
                    for (int c = 0; c < 8; c++) split1(vals[c], hh[c], ll[c]);
                    uint4 uh = make_uint4(pack2(hh[0], hh[1]), pack2(hh[2], hh[3]),
                                          pack2(hh[4], hh[5]), pack2(hh[6], hh[7]));
                    uint4 ul = make_uint4(pack2(ll[0], ll[1]), pack2(ll[2], ll[3]),
                                          pack2(ll[4], ll[5]), pack2(ll[6], ll[7]));
                    *(uint4*)(Chi + (size_t)grow * ldc + gcol) = uh;
                    *(uint4*)(Clo + (size_t)grow * ldc + gcol) = ul;
                } else {
                    *(uint4*)(Ch16 + (size_t)grow * ldc + gcol) = make_uint4(
                        pack2h(__float2half(vals[0]), __float2half(vals[1])),
                        pack2h(__float2half(vals[2]), __float2half(vals[3])),
                        pack2h(__float2half(vals[4]), __float2half(vals[5])),
                        pack2h(__float2half(vals[6]), __float2half(vals[7])));
                }
                __syncwarp();
            }
        }
}

#define GEMM_SMEM_BIG   (2 * (2 * A_TILE + 2 * (256 * PADE * 2)))
#define GEMM_SMEM_SMALL (2 * (2 * A_TILE + 2 * (128 * PADE * 2)))

// ============================================================================
// fp16 flash attention (causal): Q hi/lo + K single, P hi/lo + V single.
// ============================================================================
#define FQ_LD 136
#define FS_LD 68
#define FP_LD 72
#define FO_LD 132
#define QH_OFF 0
#define QL_OFF 17408
#define KS_OFF 34816
#define VS_OFF 52224
#define S_OFF  69632
#define PH_OFF 87040
#define PL_OFF 96256
#define OT_OFF 105472
#define FLASH_SMEM 139264

__global__ __launch_bounds__(256, 1) void flash_kernel()
{
    extern __shared__ char sm[];
    const uint32_t sb = smem_u32(sm);
    __half* Qh = (__half*)(sm + QH_OFF);
    __half* Ql = (__half*)(sm + QL_OFF);
    __half* Ks = (__half*)(sm + KS_OFF);
    __half* Vs = (__half*)(sm + VS_OFF);
    float*  Ss = (float*)(sm + S_OFF);
    __half* Ph = (__half*)(sm + PH_OFF);
    __half* Pl = (__half*)(sm + PL_OFF);
    float*  Ot = (float*)(sm + OT_OFF);

    const int qt = gridDim.x - 1 - blockIdx.x;   // heavy tiles first
    const int h  = blockIdx.y;
    const int b  = blockIdx.z;
    const int q0 = qt * 64;
    const int t  = threadIdx.x;
    const int tx = t & 15;
    const int ty = t >> 4;
    const int w  = t >> 5;
    const int wr = w >> 1;
    const int wc = w & 1;

    for (int i = t; i < 1024; i += 256) {
        const int r = i >> 4;
        const int c = (i & 15) << 3;
        const size_t g = (size_t)(b * SS + q0 + r) * HH + h * HDIM + c;
        const uint32_t so = (uint32_t)((r * FQ_LD + c) * 2);
        cp16(sb + QH_OFF + so, g_qh16 + g, 16);
        cp16(sb + QL_OFF + so, g_ql16 + g, 16);
    }
    cp_commit();

    float m_i[4], l_i[4], O[4][8];
#pragma unroll
    for (int i = 0; i < 4; i++) {
        m_i[i] = -1e30f; l_i[i] = 0.0f;
#pragma unroll
        for (int c = 0; c < 8; c++) O[i][c] = 0.0f;
    }
    const float scale = 0.08838834764831843f;

    for (int kt = 0; kt <= qt; kt++) {
        const int k0 = kt * 64;
        for (int i = t; i < 1024; i += 256) {
            const int r = i >> 4;
            const int c = (i & 15) << 3;
            const size_t g = (size_t)(b * SS + k0 + r) * HH + h * HDIM + c;
            cp16(sb + KS_OFF + (uint32_t)((r * FQ_LD + c) * 2), g_k16 + g, 16);
        }
        cp_commit();
        for (int i = t; i < 1024; i += 256) {
            const int r = i >> 4;
            const int c = (i & 15) << 3;
            const size_t g = (size_t)(b * SS + k0 + r) * HH + h * HDIM + c;
            cp16(sb + VS_OFF + (uint32_t)((r * FQ_LD + c) * 2), g_v16 + g, 16);
        }
        cp_commit();
        cp_wait<1>();
        __syncthreads();

        {
            wmma::fragment<wmma::accumulator, 16, 16, 16, float> sacc[2];
            wmma::fill_fragment(sacc[0], 0.0f);
            wmma::fill_fragment(sacc[1], 0.0f);
#pragma unroll
            for (int k = 0; k < 8; k++) {
                wmma::fragment<wmma::matrix_a, 16, 16, 16, __half, wmma::row_major> ah, al;
                wmma::load_matrix_sync(ah, Qh + (wr * 16) * FQ_LD + k * 16, FQ_LD);
                wmma::load_matrix_sync(al, Ql + (wr * 16) * FQ_LD + k * 16, FQ_LD);
#pragma unroll
                for (int jj = 0; jj < 2; jj++) {
                    const int col0 = wc * 32 + jj * 16;
                    wmma::fragment<wmma::matrix_b, 16, 16, 16, __half, wmma::col_major> bf;
                    wmma::load_matrix_sync(bf, Ks + col0 * FQ_LD + k * 16, FQ_LD);
                    wmma::mma_sync(sacc[jj], ah, bf, sacc[jj]);
                    wmma::mma_sync(sacc[jj], al, bf, sacc[jj]);
                }
            }
#pragma unroll
            for (int jj = 0; jj < 2; jj++)
                wmma::store_matrix_sync(&Ss[(wr * 16) * FS_LD + wc * 32 + jj * 16],
                                        sacc[jj], FS_LD, wmma::mem_row_major);
        }
        __syncthreads();

        float corr[4];
#pragma unroll
        for (int i = 0; i < 4; i++) {
            const int row = ty * 4 + i;
            const int qg  = q0 + row;
            float sv[4], rmax = -1e30f;
#pragma unroll
            for (int j = 0; j < 4; j++) {
                float s = Ss[row * FS_LD + tx + 16 * j] * scale;
                if (k0 + tx + 16 * j > qg) s = -1e30f;
                sv[j] = s;
                rmax = fmaxf(rmax, s);
            }
#pragma unroll
            for (int off = 8; off >= 1; off >>= 1)
                rmax = fmaxf(rmax, __shfl_xor_sync(0xffffffffu, rmax, off));
            const float mnew = fmaxf(m_i[i], rmax);
            corr[i] = __expf(m_i[i] - mnew);
            float rsum = 0.0f;
#pragma unroll
            for (int j = 0; j < 4; j++) {
                const float p = __expf(sv[j] - mnew);
                __half ph, pl;
                split1h(p, ph, pl);
                Ph[row * FP_LD + tx + 16 * j] = ph;
                Pl[row * FP_LD + tx + 16 * j] = pl;
                rsum += p;
            }
#pragma unroll
            for (int off = 8; off >= 1; off >>= 1)
                rsum += __shfl_xor_sync(0xffffffffu, rsum, off);
            l_i[i] = l_i[i] * corr[i] + rsum;
            m_i[i] = mnew;
        }
        cp_wait<0>();
        __syncthreads();

        {
            wmma::fragment<wmma::accumulator, 16, 16, 16, float> oacc[4];
#pragma unroll
            for (int jj = 0; jj < 4; jj++) wmma::fill_fragment(oacc[jj], 0.0f);
#pragma unroll
            for (int k = 0; k < 4; k++) {
                wmma::fragment<wmma::matrix_a, 16, 16, 16, __half, wmma::row_major> pah, pal;
                wmma::load_matrix_sync(pah, Ph + (wr * 16) * FP_LD + k * 16, FP_LD);
                wmma::load_matrix_sync(pal, Pl + (wr * 16) * FP_LD + k * 16, FP_LD);
#pragma unroll
                for (int jj = 0; jj < 4; jj++) {
                    const int col0 = wc * 64 + jj * 16;
                    wmma::fragment<wmma::matrix_b, 16, 16, 16, __half, wmma::row_major> vb;
                    wmma::load_matrix_sync(vb, Vs + (k * 16) * FQ_LD + col0, FQ_LD);
                    wmma::mma_sync(oacc[jj], pah, vb, oacc[jj]);
                    wmma::mma_sync(oacc[jj], pal, vb, oacc[jj]);
                }
            }
#pragma unroll
            for (int jj = 0; jj < 4; jj++)
                wmma::store_matrix_sync(&Ot[(wr * 16) * FO_LD + wc * 64 + jj * 16],
                                        oacc[jj], FO_LD, wmma::mem_row_major);
        }
        __syncthreads();

#pragma unroll
        for (int i = 0; i < 4; i++) {
            const int row = ty * 4 + i;
#pragma unroll
            for (int c = 0; c < 8; c++)
                O[i][c] = O[i][c] * corr[i] + Ot[row * FO_LD + tx * 8 + c];
        }
    }

#pragma unroll
    for (int i = 0; i < 4; i++) {
        const float inv = 1.0f / l_i[i];
        const int qg = q0 + ty * 4 + i;
        const size_t o = (size_t)(b * SS + qg) * HH + h * HDIM + tx * 8;
        __half hh[8], ll[8];
#pragma unroll
        for (int c = 0; c < 8; c++) split1h(O[i][c] * inv, hh[c], ll[c]);
        *(uint4*)(g_ah16 + o) = make_uint4(pack2h(hh[0], hh[1]), pack2h(hh[2], hh[3]),
                                           pack2h(hh[4], hh[5]), pack2h(hh[6], hh[7]));
        *(uint4*)(g_al16 + o) = make_uint4(pack2h(ll[0], ll[1]), pack2h(ll[2], ll[3]),
                                           pack2h(ll[4], ll[5]), pack2h(ll[6], ll[7]));
    }
}

// ============================================================================
// Launch
// ============================================================================
extern "C" void kernel_launch(void* const* d_in, const int* in_sizes, int n_in,
                              void* d_out, int out_size)
{
    const float* x    = (const float*)d_in[0];
    const float* Wqkv = (const float*)d_in[1];
    const float* bqkv = (const float*)d_in[2];
    const float* Wc   = (const float*)d_in[3];
    const float* bc   = (const float*)d_in[4];
    const float* Wr   = (const float*)d_in[5];
    const float* br   = (const float*)d_in[6];
    const float* Wd   = (const float*)d_in[7];
    const float* bd   = (const float*)d_in[8];
    float* out = (float*)d_out;

    float* qkv;
    cudaGetSymbolAddress((void**)&qkv, g_qkv);
    __half *x16, *wq16, *wd16, *ah16, *al16, *v16;
    cudaGetSymbolAddress((void**)&x16,  g_x16);
    cudaGetSymbolAddress((void**)&wq16, g_wq16);
    cudaGetSymbolAddress((void**)&wd16, g_wd16);
    cudaGetSymbolAddress((void**)&ah16, g_ah16);
    cudaGetSymbolAddress((void**)&al16, g_al16);
    cudaGetSymbolAddress((void**)&v16,  g_v16);
    __nv_bfloat16 *vh, *vl, *wch, *wcl, *vch, *vcl, *wrh, *wrl;
    cudaGetSymbolAddress((void**)&vh,  g_vh);  cudaGetSymbolAddress((void**)&vl,  g_vl);
    cudaGetSymbolAddress((void**)&wch, g_wch); cudaGetSymbolAddress((void**)&wcl, g_wcl);
    cudaGetSymbolAddress((void**)&vch, g_vch); cudaGetSymbolAddress((void**)&vcl, g_vcl);
    cudaGetSymbolAddress((void**)&wrh, g_wrh); cudaGetSymbolAddress((void**)&wrl, g_wrl);

    cudaFuncSetAttribute(gemm_f16_kernel<1>,
                         cudaFuncAttributeMaxDynamicSharedMemorySize, GEMM16_SMEM_1);
    cudaFuncSetAttribute(gemm_f16_kernel<2>,
                         cudaFuncAttributeMaxDynamicSharedMemorySize, GEMM16_SMEM_2);
    cudaFuncSetAttribute(gemm_wmma_kernel<32>,
                         cudaFuncAttributeMaxDynamicSharedMemorySize, GEMM_SMEM_BIG);
    cudaFuncSetAttribute(gemm_wmma_kernel<16>,
                         cudaFuncAttributeMaxDynamicSharedMemorySize, GEMM_SMEM_SMALL);
    cudaFuncSetAttribute(flash_kernel,
                         cudaFuncAttributeMaxDynamicSharedMemorySize, FLASH_SMEM);

    // #1-#5: conversions
    conv_f16_kernel<<<(MALL * HH / 4 + 255) / 256, 256>>>(x, x16, MALL * HH);
    conv_f16_kernel<<<(H3 * HH / 4 + 255) / 256, 256>>>(Wqkv, wq16, H3 * HH);
    split_kernel<<<(VP * HH / 4 + 255) / 256, 256>>>(Wc, wch, wcl, VP * HH);
    split_kernel<<<(HH * VP / 4 + 255) / 256, 256>>>(Wr, wrh, wrl, HH * VP);
    conv_f16_kernel<<<(HH * HH / 4 + 255) / 256, 256>>>(Wd, wd16, HH * HH);

    // #6: qkv = x @ Wqkv^T + bqkv (single-pass fp16)  <-- ncu -s 5 captures this
    gemm_f16_kernel<1><<<dim3(H3 / 256, MALL / 128), 512, GEMM16_SMEM_1>>>(
        x16, nullptr, wq16, bqkv, qkv, H3, H3, HH);

    // #7: fused RoPE -> q fp16 hi/lo, k fp16
    rope_split_kernel<<<BB * SS * NHEAD / 8, 256>>>();

    // #8-#9: vc = v @ Wc^T + bc (3-term bf16 -> bf16 hi/lo)
    split_v_kernel<<<(MALL * HH / 4 + 255) / 256, 256>>>();
    gemm_wmma_kernel<16><<<dim3((VP + 127) / 128, MALL / 128), 512, GEMM_SMEM_SMALL>>>(
        vh, vl, wch, wcl, bc, nullptr, vch, vcl, nullptr, VP, VP, HH);

    // #10: vr = vc @ Wr^T + br (3-term bf16 -> fp16 single)
    gemm_wmma_kernel<32><<<dim3(HH / 256, MALL / 128), 512, GEMM_SMEM_BIG>>>(
        vch, vcl, wrh, wrl, br, nullptr, nullptr, nullptr, v16, HH, HH, VP);

    // #11: flash attention (2-term fp16) -> fp16 hi/lo att
    flash_kernel<<<dim3(SS / 64, NHEAD, BB), 256, FLASH_SMEM>>>();

    // #12: out = att @ Wd^T + bd (2-term fp16)
    gemm_f16_kernel<2><<<dim3(HH / 256, MALL / 128), 512, GEMM16_SMEM_2>>>(
        ah16, al16, wd16, bd, out, HH, HH, HH);
}

// round 16
// speedup vs baseline: 1.3191x; 1.3191x over previous
#include <cuda_runtime.h>
#include <cuda_fp16.h>
#include <mma.h>
#include <math.h>
#include <stdint.h>

using namespace nvcuda;

// Problem constants
#define BB 2
#define SS 2048
#define HH 2048
#define NHEAD 16
#define HDIM 128
#define H3 6144
#define VP 320
#define MALL 4096

// -------- fp32 scratch --------
__device__ float g_qkv[BB * SS * H3];

// -------- fp16 operands --------
__device__ __half g_xh16[MALL * HH], g_xl16[MALL * HH];   // x hi/lo (QKV A)
__device__ __half g_wq16[H3 * HH];
__device__ __half g_wd16[HH * HH];
__device__ __half g_wc16[VP * HH];
__device__ __half g_wr16[HH * VP];
__device__ __half g_svh [MALL * HH], g_svl [MALL * HH];   // v slice hi/lo (Vc A)
__device__ __half g_vch16[MALL * VP], g_vcl16[MALL * VP]; // vc hi/lo (Vr A)
__device__ __half g_ah16[MALL * HH], g_al16[MALL * HH];   // flash output att hi/lo
__device__ __half g_qh16[MALL * HH], g_ql16[MALL * HH];   // roped q hi/lo
__device__ __half g_k16 [MALL * HH];                      // roped k single
__device__ __half g_v16 [MALL * HH];                      // restored v single

// ============================================================================
// helpers
// ============================================================================
__device__ __forceinline__ uint32_t smem_u32(const void* p) {
    uint32_t a;
    asm("{ .reg .u64 t; cvta.to.shared.u64 t, %1; cvt.u32.u64 %0, t; }"
        : "=r"(a) : "l"(p));
    return a;
}
__device__ __forceinline__ void cp16(uint32_t s, const void* g, uint32_t nbytes) {
    asm volatile("cp.async.cg.shared.global [%0], [%1], 16, %2;"
                 :: "r"(s), "l"(g), "r"(nbytes) : "memory");
}
__device__ __forceinline__ void cp_commit() {
    asm volatile("cp.async.commit_group;" ::: "memory");
}
template <int N>
__device__ __forceinline__ void cp_wait() {
    asm volatile("cp.async.wait_group %0;" :: "n"(N) : "memory");
}
__device__ __forceinline__ void split1h(float v, __half& h, __half& l) {
    h = __float2half(v);
    l = __float2half(v - __half2float(h));
}
__device__ __forceinline__ uint32_t pack2h(__half a, __half b) {
    return (uint32_t)__half_as_ushort(a) |
           ((uint32_t)__half_as_ushort(b) << 16);
}

// ============================================================================
// conversion kernels
// ============================================================================
__global__ void split_f16_kernel(const float* __restrict__ src,
                                 __half* __restrict__ hi,
                                 __half* __restrict__ lo, int n)
{
    int i = (blockIdx.x * blockDim.x + threadIdx.x) * 4;
    if (i >= n) return;
    float4 v = *(const float4*)(src + i);
    __half h0, h1, h2, h3, l0, l1, l2, l3;
    split1h(v.x, h0, l0); split1h(v.y, h1, l1);
    split1h(v.z, h2, l2); split1h(v.w, h3, l3);
    *(uint2*)(hi + i) = make_uint2(pack2h(h0, h1), pack2h(h2, h3));
    *(uint2*)(lo + i) = make_uint2(pack2h(l0, l1), pack2h(l2, l3));
}

__global__ void conv_f16_kernel(const float* __restrict__ src,
                                __half* __restrict__ dst, int n)
{
    int i = (blockIdx.x * blockDim.x + threadIdx.x) * 4;
    if (i >= n) return;
    float4 v = *(const float4*)(src + i);
    *(uint2*)(dst + i) = make_uint2(pack2h(__float2half(v.x), __float2half(v.y)),
                                    pack2h(__float2half(v.z), __float2half(v.w)));
}

// v slice of g_qkv (strided) -> contiguous fp16 hi/lo [MALL x HH]
__global__ void split_v16_kernel()
{
    int i = (blockIdx.x * blockDim.x + threadIdx.x) * 4;
    if (i >= MALL * HH) return;
    int r = i / HH, c = i % HH;
    float4 v = *(const float4*)(g_qkv + (size_t)r * H3 + 2 * HH + c);
    __half h0, h1, h2, h3, l0, l1, l2, l3;
    split1h(v.x, h0, l0); split1h(v.y, h1, l1);
    split1h(v.z, h2, l2); split1h(v.w, h3, l3);
    *(uint2*)(g_svh + i) = make_uint2(pack2h(h0, h1), pack2h(h2, h3));
    *(uint2*)(g_svl + i) = make_uint2(pack2h(l0, l1), pack2h(l2, l3));
}

// ============================================================================
// fused RoPE + convert: q -> fp16 hi/lo, k -> fp16 single
// ============================================================================
__global__ void rope_split_kernel()
{
    const int gw   = blockIdx.x * 8 + (threadIdx.x >> 5);
    const int lane = threadIdx.x & 31;
    const int h = gw & 15;
    const int s = (gw >> 4) & 2047;
    const int b = gw >> 15;

    const size_t qbase = (size_t)(b * SS + s) * H3 + h * HDIM;
    const int d0 = lane * 4;
    float4 q = *(const float4*)(g_qkv + qbase + d0);
    float4 k = *(const float4*)(g_qkv + qbase + HH + d0);

    float4 qp, kp;
    qp.x = __shfl_xor_sync(0xffffffffu, q.x, 4);
    qp.y = __shfl_xor_sync(0xffffffffu, q.y, 4);
    qp.z = __shfl_xor_sync(0xffffffffu, q.z, 4);
    qp.w = __shfl_xor_sync(0xffffffffu, q.w, 4);
    kp.x = __shfl_xor_sync(0xffffffffu, k.x, 4);
    kp.y = __shfl_xor_sync(0xffffffffu, k.y, 4);
    kp.z = __shfl_xor_sync(0xffffffffu, k.z, 4);
    kp.w = __shfl_xor_sync(0xffffffffu, k.w, 4);

    if (lane < 8) {
        const float sgn = (lane < 4) ? -1.0f : 1.0f;
        float qa[4] = {q.x, q.y, q.z, q.w};
        float pa[4] = {qp.x, qp.y, qp.z, qp.w};
        float ka[4] = {k.x, k.y, k.z, k.w};
        float kb[4] = {kp.x, kp.y, kp.z, kp.w};
#pragma unroll
        for (int i = 0; i < 4; i++) {
            int j = (lane & 3) * 4 + i;
            float inv = __expf(-(float)(2 * j) * (9.210340371976184f / 32.0f));
            float sn, cs;
            sincosf((float)s * inv, &sn, &cs);
            qa[i] = qa[i] * cs + sgn * pa[i] * sn;
            ka[i] = ka[i] * cs + sgn * kb[i] * sn;
        }
        q = make_float4(qa[0], qa[1], qa[2], qa[3]);
        k = make_float4(ka[0], ka[1], ka[2], ka[3]);
    }

    const size_t o = (size_t)(b * SS + s) * HH + h * HDIM + d0;
    __half h0, h1, h2, h3, l0, l1, l2, l3;
    split1h(q.x, h0, l0); split1h(q.y, h1, l1);
    split1h(q.z, h2, l2); split1h(q.w, h3, l3);
    *(uint2*)(g_qh16 + o) = make_uint2(pack2h(h0, h1), pack2h(h2, h3));
    *(uint2*)(g_ql16 + o) = make_uint2(pack2h(l0, l1), pack2h(l2, l3));
    *(uint2*)(g_k16 + o)  = make_uint2(pack2h(__float2half(k.x), __float2half(k.y)),
                                       pack2h(__float2half(k.z), __float2half(k.w)));
}

// ============================================================================
// Unified fp16 GEMM: C = (Ah [+ Al]) @ B^T + bias.
// NA: A terms (1 or 2). WN: warp N-width (16 -> BN=128, 32 -> BN=256).
// OUT: 0 = fp32 C, 1 = fp16 hi/lo (Chi, Clo), 2 = fp16 single (C16).
// 128 x BN CTA tile, 512 threads (2x8 warps), K-chunk 32, 2-stage cp.async.
// ============================================================================
#define PADH     40
#define A_TILE_H (128 * PADH * 2)          // 10240 B

template <int NA, int WN, int OUT>
__global__ __launch_bounds__(512, 1) void gemm_f16_kernel(
    const __half* __restrict__ Ah, const __half* __restrict__ Al,
    const __half* __restrict__ Bw,
    const float* __restrict__ bias,
    float* __restrict__ C,
    __half* __restrict__ Chi, __half* __restrict__ Clo,
    __half* __restrict__ C16,
    int ldc, int N, int K)
{
    constexpr int BN     = WN * 8;
    constexpr int B_TILE = BN * PADH * 2;
    constexpr int STAGE  = NA * A_TILE_H + B_TILE;
    constexpr int NJ     = WN / 16;

    extern __shared__ char smem[];
    const uint32_t sbase = smem_u32(smem);
    const int t    = threadIdx.x;
    const int w    = t >> 5;
    const int lane = t & 31;
    const int wm   = w >> 3;
    const int wn   = w & 7;
    const int m0   = blockIdx.y * 128;
    const int n0   = blockIdx.x * BN;

    wmma::fragment<wmma::accumulator, 16, 16, 16, float> acc[4][NJ];
#pragma unroll
    for (int i = 0; i < 4; i++)
#pragma unroll
        for (int j = 0; j < NJ; j++) wmma::fill_fragment(acc[i][j], 0.0f);

    const int nchunks = K / 32;

    auto load_stage = [&](int chunk, int stage) {
        const int kk = chunk * 32;
        const uint32_t sst = sbase + stage * STAGE;
        // A tiles: NA x 512 cp16
#pragma unroll
        for (int rep = 0; rep < NA; rep++) {
            const int v = t + rep * 512;
            const int tile = v >> 9;
            const int r = (v >> 2) & 127;
            const int c = (v & 3) * 8;
            const __half* src = tile ? Al : Ah;
            cp16(sst + tile * A_TILE_H + r * (PADH * 2) + c * 2,
                 src + (size_t)(m0 + r) * K + kk + c, 16);
        }
        // B tile: BN*4 cp16
        constexpr int BREP = BN / 128;
#pragma unroll
        for (int rep = 0; rep < BREP; rep++) {
            const int v = t + rep * 512;
            const int r = v >> 2;
            const int c = (v & 3) * 8;
            const int brow = n0 + r;
            const uint32_t vb = (brow < N) ? 16u : 0u;
            cp16(sst + NA * A_TILE_H + r * (PADH * 2) + c * 2,
                 Bw + (size_t)(brow < N ? brow : 0) * K + kk + c, vb);
        }
        cp_commit();
    };

    load_stage(0, 0);

    for (int chunk = 0; chunk < nchunks; chunk++) {
        const int stage = chunk & 1;
        if (chunk + 1 < nchunks) { load_stage(chunk + 1, stage ^ 1); cp_wait<1>(); }
        else cp_wait<0>();
        __syncthreads();

        const __half* sAh = (const __half*)(smem + stage * STAGE);
        const __half* sAl = (const __half*)(smem + stage * STAGE + A_TILE_H);
        const __half* sB  = (const __half*)(smem + stage * STAGE + NA * A_TILE_H);

#pragma unroll
        for (int ks = 0; ks < 2; ks++) {
            wmma::fragment<wmma::matrix_b, 16, 16, 16, __half, wmma::col_major> bf[NJ];
#pragma unroll
            for (int j = 0; j < NJ; j++) {
                const int col = wn * WN + j * 16;
                wmma::load_matrix_sync(bf[j], sB + col * PADH + ks * 16, PADH);
            }
#pragma unroll
            for (int i = 0; i < 4; i++) {
                const int row = wm * 64 + i * 16;
                wmma::fragment<wmma::matrix_a, 16, 16, 16, __half, wmma::row_major> ah;
                wmma::load_matrix_sync(ah, sAh + row * PADH + ks * 16, PADH);
#pragma unroll
                for (int j = 0; j < NJ; j++)
                    wmma::mma_sync(acc[i][j], ah, bf[j], acc[i][j]);
                if (NA == 2) {
                    wmma::fragment<wmma::matrix_a, 16, 16, 16, __half, wmma::row_major> al;
                    wmma::load_matrix_sync(al, sAl + row * PADH + ks * 16, PADH);
#pragma unroll
                    for (int j = 0; j < NJ; j++)
                        wmma::mma_sync(acc[i][j], al, bf[j], acc[i][j]);
                }
            }
        }
        __syncthreads();
    }

    // epilogue: per-warp 16x16 staging in smem
    float* epi = (float*)(smem) + w * 256;
#pragma unroll
    for (int i = 0; i < 4; i++)
#pragma unroll
        for (int j = 0; j < NJ; j++) {
            const int gcol0 = n0 + wn * WN + j * 16;
            if (gcol0 < N) {
                wmma::store_matrix_sync(epi, acc[i][j], 16, wmma::mem_row_major);
                __syncwarp();
                const int row  = lane >> 1;
                const int coff = (lane & 1) * 8;
                const int grow = m0 + wm * 64 + i * 16 + row;
                const int gcol = gcol0 + coff;
                float4 b0 = *(const float4*)(bias + gcol);
                float4 b1 = *(const float4*)(bias + gcol + 4);
                const float* e = epi + row * 16 + coff;
                float vals[8] = {e[0] + b0.x, e[1] + b0.y, e[2] + b0.z, e[3] + b0.w,
                                 e[4] + b1.x, e[5] + b1.y, e[6] + b1.z, e[7] + b1.w};
                if (OUT == 0) {
                    float* cp = C + (size_t)grow * ldc + gcol;
                    *(float4*)cp       = make_float4(vals[0], vals[1], vals[2], vals[3]);
                    *(float4*)(cp + 4) = make_float4(vals[4], vals[5], vals[6], vals[7]);
                } else if (OUT == 1) {
                    __half hh[8], ll[8];
#pragma unroll
                    for (int c = 0; c < 8; c++) split1h(vals[c], hh[c], ll[c]);
                    *(uint4*)(Chi + (size_t)grow * ldc + gcol) = make_uint4(
                        pack2h(hh[0], hh[1]), pack2h(hh[2], hh[3]),
                        pack2h(hh[4], hh[5]), pack2h(hh[6], hh[7]));
                    *(uint4*)(Clo + (size_t)grow * ldc + gcol) = make_uint4(
                        pack2h(ll[0], ll[1]), pack2h(ll[2], ll[3]),
                        pack2h(ll[4], ll[5]), pack2h(ll[6], ll[7]));
                } else {
                    *(uint4*)(C16 + (size_t)grow * ldc + gcol) = make_uint4(
                        pack2h(__float2half(vals[0]), __float2half(vals[1])),
                        pack2h(__float2half(vals[2]), __float2half(vals[3])),
                        pack2h(__float2half(vals[4]), __float2half(vals[5])),
                        pack2h(__float2half(vals[6]), __float2half(vals[7])));
                }
                __syncwarp();
            }
        }
}

#define GEMM_SMEM_2_32 (2 * (2 * A_TILE_H + 256 * PADH * 2))   // 81920
#define GEMM_SMEM_2_16 (2 * (2 * A_TILE_H + 128 * PADH * 2))   // 61440

// ============================================================================
// fp16 flash attention (causal): Q hi/lo + K single, P hi/lo + V single.
// (identical to the 1664us R13 version)
// ============================================================================
#define FQ_LD 136
#define FS_LD 68
#define FP_LD 72
#define FO_LD 132
#define QH_OFF 0
#define QL_OFF 17408
#define KS_OFF 34816
#define VS_OFF 52224
#define S_OFF  69632
#define PH_OFF 87040
#define PL_OFF 96256
#define OT_OFF 105472
#define FLASH_SMEM 139264

__global__ __launch_bounds__(256, 1) void flash_kernel()
{
    extern __shared__ char sm[];
    const uint32_t sb = smem_u32(sm);
    __half* Qh = (__half*)(sm + QH_OFF);
    __half* Ql = (__half*)(sm + QL_OFF);
    __half* Ks = (__half*)(sm + KS_OFF);
    __half* Vs = (__half*)(sm + VS_OFF);
    float*  Ss = (float*)(sm + S_OFF);
    __half* Ph = (__half*)(sm + PH_OFF);
    __half* Pl = (__half*)(sm + PL_OFF);
    float*  Ot = (float*)(sm + OT_OFF);

    const int qt = gridDim.x - 1 - blockIdx.x;   // heavy tiles first
    const int h  = blockIdx.y;
    const int b  = blockIdx.z;
    const int q0 = qt * 64;
    const int t  = threadIdx.x;
    const int tx = t & 15;
    const int ty = t >> 4;
    const int w  = t >> 5;
    const int wr = w >> 1;
    const int wc = w & 1;

    for (int i = t; i < 1024; i += 256) {
        const int r = i >> 4;
        const int c = (i & 15) << 3;
        const size_t g = (size_t)(b * SS + q0 + r) * HH + h * HDIM + c;
        const uint32_t so = (uint32_t)((r * FQ_LD + c) * 2);
        cp16(sb + QH_OFF + so, g_qh16 + g, 16);
        cp16(sb + QL_OFF + so, g_ql16 + g, 16);
    }
    cp_commit();

    float m_i[4], l_i[4], O[4][8];
#pragma unroll
    for (int i = 0; i < 4; i++) {
        m_i[i] = -1e30f; l_i[i] = 0.0f;
#pragma unroll
        for (int c = 0; c < 8; c++) O[i][c] = 0.0f;
    }
    const float scale = 0.08838834764831843f;

    for (int kt = 0; kt <= qt; kt++) {
        const int k0 = kt * 64;
        for (int i = t; i < 1024; i += 256) {
            const int r = i >> 4;
            const int c = (i & 15) << 3;
            const size_t g = (size_t)(b * SS + k0 + r) * HH + h * HDIM + c;
            cp16(sb + KS_OFF + (uint32_t)((r * FQ_LD + c) * 2), g_k16 + g, 16);
        }
        cp_commit();
        for (int i = t; i < 1024; i += 256) {
            const int r = i >> 4;
            const int c = (i & 15) << 3;
            const size_t g = (size_t)(b * SS + k0 + r) * HH + h * HDIM + c;
            cp16(sb + VS_OFF + (uint32_t)((r * FQ_LD + c) * 2), g_v16 + g, 16);
        }
        cp_commit();
        cp_wait<1>();
        __syncthreads();

        {
            wmma::fragment<wmma::accumulator, 16, 16, 16, float> sacc[2];
            wmma::fill_fragment(sacc[0], 0.0f);
            wmma::fill_fragment(sacc[1], 0.0f);
#pragma unroll
            for (int k = 0; k < 8; k++) {
                wmma::fragment<wmma::matrix_a, 16, 16, 16, __half, wmma::row_major> ah, al;
                wmma::load_matrix_sync(ah, Qh + (wr * 16) * FQ_LD + k * 16, FQ_LD);
                wmma::load_matrix_sync(al, Ql + (wr * 16) * FQ_LD + k * 16, FQ_LD);
#pragma unroll
                for (int jj = 0; jj < 2; jj++) {
                    const int col0 = wc * 32 + jj * 16;
                    wmma::fragment<wmma::matrix_b, 16, 16, 16, __half, wmma::col_major> bf;
                    wmma::load_matrix_sync(bf, Ks + col0 * FQ_LD + k * 16, FQ_LD);
                    wmma::mma_sync(sacc[jj], ah, bf, sacc[jj]);
                    wmma::mma_sync(sacc[jj], al, bf, sacc[jj]);
                }
            }
#pragma unroll
            for (int jj = 0; jj < 2; jj++)
                wmma::store_matrix_sync(&Ss[(wr * 16) * FS_LD + wc * 32 + jj * 16],
                                        sacc[jj], FS_LD, wmma::mem_row_major);
        }
        __syncthreads();

        float corr[4];
#pragma unroll
        for (int i = 0; i < 4; i++) {
            const int row = ty * 4 + i;
            const int qg  = q0 + row;
            float sv[4], rmax = -1e30f;
#pragma unroll
            for (int j = 0; j < 4; j++) {
                float s = Ss[row * FS_LD + tx + 16 * j] * scale;
                if (k0 + tx + 16 * j > qg) s = -1e30f;
                sv[j] = s;
                rmax = fmaxf(rmax, s);
            }
#pragma unroll
            for (int off = 8; off >= 1; off >>= 1)
                rmax = fmaxf(rmax, __shfl_xor_sync(0xffffffffu, rmax, off));
            const float mnew = fmaxf(m_i[i], rmax);
            corr[i] = __expf(m_i[i] - mnew);
            float rsum = 0.0f;
#pragma unroll
            for (int j = 0; j < 4; j++) {
                const float p = __expf(sv[j] - mnew);
                __half ph, pl;
                split1h(p, ph, pl);
                Ph[row * FP_LD + tx + 16 * j] = ph;
                Pl[row * FP_LD + tx + 16 * j] = pl;
                rsum += p;
            }
#pragma unroll
            for (int off = 8; off >= 1; off >>= 1)
                rsum += __shfl_xor_sync(0xffffffffu, rsum, off);
            l_i[i] = l_i[i] * corr[i] + rsum;
            m_i[i] = mnew;
        }
        cp_wait<0>();
        __syncthreads();

        {
            wmma::fragment<wmma::accumulator, 16, 16, 16, float> oacc[4];
#pragma unroll
            for (int jj = 0; jj < 4; jj++) wmma::fill_fragment(oacc[jj], 0.0f);
#pragma unroll
            for (int k = 0; k < 4; k++) {
                wmma::fragment<wmma::matrix_a, 16, 16, 16, __half, wmma::row_major> pah, pal;
                wmma::load_matrix_sync(pah, Ph + (wr * 16) * FP_LD + k * 16, FP_LD);
                wmma::load_matrix_sync(pal, Pl + (wr * 16) * FP_LD + k * 16, FP_LD);
#pragma unroll
                for (int jj = 0; jj < 4; jj++) {
                    const int col0 = wc * 64 + jj * 16;
                    wmma::fragment<wmma::matrix_b, 16, 16, 16, __half, wmma::row_major> vb;
                    wmma::load_matrix_sync(vb, Vs + (k * 16) * FQ_LD + col0, FQ_LD);
                    wmma::mma_sync(oacc[jj], pah, vb, oacc[jj]);
                    wmma::mma_sync(oacc[jj], pal, vb, oacc[jj]);
                }
            }
#pragma unroll
            for (int jj = 0; jj < 4; jj++)
                wmma::store_matrix_sync(&Ot[(wr * 16) * FO_LD + wc * 64 + jj * 16],
                                        oacc[jj], FO_LD, wmma::mem_row_major);
        }
        __syncthreads();

#pragma unroll
        for (int i = 0; i < 4; i++) {
            const int row = ty * 4 + i;
#pragma unroll
            for (int c = 0; c < 8; c++)
                O[i][c] = O[i][c] * corr[i] + Ot[row * FO_LD + tx * 8 + c];
        }
    }

#pragma unroll
    for (int i = 0; i < 4; i++) {
        const float inv = 1.0f / l_i[i];
        const int qg = q0 + ty * 4 + i;
        const size_t o = (size_t)(b * SS + qg) * HH + h * HDIM + tx * 8;
        __half hh[8], ll[8];
#pragma unroll
        for (int c = 0; c < 8; c++) split1h(O[i][c] * inv, hh[c], ll[c]);
        *(uint4*)(g_ah16 + o) = make_uint4(pack2h(hh[0], hh[1]), pack2h(hh[2], hh[3]),
                                           pack2h(hh[4], hh[5]), pack2h(hh[6], hh[7]));
        *(uint4*)(g_al16 + o) = make_uint4(pack2h(ll[0], ll[1]), pack2h(ll[2], ll[3]),
                                           pack2h(ll[4], ll[5]), pack2h(ll[6], ll[7]));
    }
}

// ============================================================================
// Launch
// ============================================================================
extern "C" void kernel_launch(void* const* d_in, const int* in_sizes, int n_in,
                              void* d_out, int out_size)
{
    const float* x    = (const float*)d_in[0];
    const float* Wqkv = (const float*)d_in[1];
    const float* bqkv = (const float*)d_in[2];
    const float* Wc   = (const float*)d_in[3];
    const float* bc   = (const float*)d_in[4];
    const float* Wr   = (const float*)d_in[5];
    const float* br   = (const float*)d_in[6];
    const float* Wd   = (const float*)d_in[7];
    const float* bd   = (const float*)d_in[8];
    float* out = (float*)d_out;

    float* qkv;
    cudaGetSymbolAddress((void**)&qkv, g_qkv);
    __half *xh16, *xl16, *wq16, *wd16, *wc16, *wr16,
           *svh, *svl, *vch16, *vcl16, *ah16, *al16, *v16;
    cudaGetSymbolAddress((void**)&xh16,  g_xh16);
    cudaGetSymbolAddress((void**)&xl16,  g_xl16);
    cudaGetSymbolAddress((void**)&wq16,  g_wq16);
    cudaGetSymbolAddress((void**)&wd16,  g_wd16);
    cudaGetSymbolAddress((void**)&wc16,  g_wc16);
    cudaGetSymbolAddress((void**)&wr16,  g_wr16);
    cudaGetSymbolAddress((void**)&svh,   g_svh);
    cudaGetSymbolAddress((void**)&svl,   g_svl);
    cudaGetSymbolAddress((void**)&vch16, g_vch16);
    cudaGetSymbolAddress((void**)&vcl16, g_vcl16);
    cudaGetSymbolAddress((void**)&ah16,  g_ah16);
    cudaGetSymbolAddress((void**)&al16,  g_al16);
    cudaGetSymbolAddress((void**)&v16,   g_v16);

    cudaFuncSetAttribute((const void*)gemm_f16_kernel<2, 32, 0>,
                         cudaFuncAttributeMaxDynamicSharedMemorySize, GEMM_SMEM_2_32);
    cudaFuncSetAttribute((const void*)gemm_f16_kernel<2, 16, 1>,
                         cudaFuncAttributeMaxDynamicSharedMemorySize, GEMM_SMEM_2_16);
    cudaFuncSetAttribute((const void*)gemm_f16_kernel<2, 32, 2>,
                         cudaFuncAttributeMaxDynamicSharedMemorySize, GEMM_SMEM_2_32);
    cudaFuncSetAttribute((const void*)flash_kernel,
                         cudaFuncAttributeMaxDynamicSharedMemorySize, FLASH_SMEM);

    // #1-#5: conversions
    split_f16_kernel<<<(MALL * HH / 4 + 255) / 256, 256>>>(x, xh16, xl16, MALL * HH);
    conv_f16_kernel<<<(H3 * HH / 4 + 255) / 256, 256>>>(Wqkv, wq16, H3 * HH);
    conv_f16_kernel<<<(VP * HH / 4 + 255) / 256, 256>>>(Wc, wc16, VP * HH);
    conv_f16_kernel<<<(HH * VP / 4 + 255) / 256, 256>>>(Wr, wr16, HH * VP);
    conv_f16_kernel<<<(HH * HH / 4 + 255) / 256, 256>>>(Wd, wd16, HH * HH);

    // #6: qkv = x @ Wqkv^T + bqkv (2-term fp16 -> fp32)
    gemm_f16_kernel<2, 32, 0><<<dim3(H3 / 256, MALL / 128), 512, GEMM_SMEM_2_32>>>(
        xh16, xl16, wq16, bqkv, qkv, nullptr, nullptr, nullptr, H3, H3, HH);

    // #7: fused RoPE -> q fp16 hi/lo, k fp16
    rope_split_kernel<<<BB * SS * NHEAD / 8, 256>>>();

    // #8: v slice -> fp16 hi/lo
    split_v16_kernel<<<(MALL * HH / 4 + 255) / 256, 256>>>();

    // #9: vc = v @ Wc^T + bc (2-term fp16 -> fp16 hi/lo), N=320, BN=128
    gemm_f16_kernel<2, 16, 1><<<dim3((VP + 127) / 128, MALL / 128), 512, GEMM_SMEM_2_16>>>(
        svh, svl, wc16, bc, nullptr, vch16, vcl16, nullptr, VP, VP, HH);

    // #10: vr = vc @ Wr^T + br (2-term fp16 -> fp16 single), K=320
    gemm_f16_kernel<2, 32, 2><<<dim3(HH / 256, MALL / 128), 512, GEMM_SMEM_2_32>>>(
        vch16, vcl16, wr16, br, nullptr, nullptr, nullptr, v16, HH, HH, VP);

    // #11: flash attention (2-term fp16) -> fp16 hi/lo att
    flash_kernel<<<dim3(SS / 64, NHEAD, BB), 256, FLASH_SMEM>>>();

    // #12: out = att @ Wd^T + bd (2-term fp16 -> fp32)
    gemm_f16_kernel<2, 32, 0><<<dim3(HH / 256, MALL / 128), 512, GEMM_SMEM_2_32>>>(
        ah16, al16, wd16, bd, out, nullptr, nullptr, nullptr, HH, HH, HH);
}

// round 17
// speedup vs baseline: 1.3744x; 1.0420x over previous
#include <cuda_runtime.h>
#include <cuda_fp16.h>
#include <mma.h>
#include <math.h>
#include <stdint.h>

using namespace nvcuda;

// Problem constants
#define BB 2
#define SS 2048
#define HH 2048
#define NHEAD 16
#define HDIM 128
#define H3 6144
#define VP 320
#define MALL 4096

// -------- fp32 scratch --------
__device__ float g_qkv[BB * SS * H3];

// -------- fp16 operands --------
__device__ __half g_xh16[MALL * HH], g_xl16[MALL * HH];   // x hi/lo (QKV A)
__device__ __half g_wq16[H3 * HH];
__device__ __half g_wd16[HH * HH];
__device__ __half g_wc16[VP * HH];
__device__ __half g_wr16[HH * VP];
__device__ __half g_svh [MALL * HH], g_svl [MALL * HH];   // v slice hi/lo (Vc A)
__device__ __half g_vch16[MALL * VP], g_vcl16[MALL * VP]; // vc hi/lo (Vr A)
__device__ __half g_ah16[MALL * HH], g_al16[MALL * HH];   // flash output att hi/lo
__device__ __half g_q16 [MALL * HH];                      // roped q single
__device__ __half g_k16 [MALL * HH];                      // roped k single
__device__ __half g_v16 [MALL * HH];                      // restored v single

// ============================================================================
// helpers
// ============================================================================
__device__ __forceinline__ uint32_t smem_u32(const void* p) {
    uint32_t a;
    asm("{ .reg .u64 t; cvta.to.shared.u64 t, %1; cvt.u32.u64 %0, t; }"
        : "=r"(a) : "l"(p));
    return a;
}
__device__ __forceinline__ void cp16(uint32_t s, const void* g, uint32_t nbytes) {
    asm volatile("cp.async.cg.shared.global [%0], [%1], 16, %2;"
                 :: "r"(s), "l"(g), "r"(nbytes) : "memory");
}
__device__ __forceinline__ void cp_commit() {
    asm volatile("cp.async.commit_group;" ::: "memory");
}
template <int N>
__device__ __forceinline__ void cp_wait() {
    asm volatile("cp.async.wait_group %0;" :: "n"(N) : "memory");
}
__device__ __forceinline__ void split1h(float v, __half& h, __half& l) {
    h = __float2half(v);
    l = __float2half(v - __half2float(h));
}
__device__ __forceinline__ uint32_t pack2h(__half a, __half b) {
    return (uint32_t)__half_as_ushort(a) |
           ((uint32_t)__half_as_ushort(b) << 16);
}

// ============================================================================
// conversion kernels
// ============================================================================
__global__ void split_f16_kernel(const float* __restrict__ src,
                                 __half* __restrict__ hi,
                                 __half* __restrict__ lo, int n)
{
    int i = (blockIdx.x * blockDim.x + threadIdx.x) * 4;
    if (i >= n) return;
    float4 v = *(const float4*)(src + i);
    __half h0, h1, h2, h3, l0, l1, l2, l3;
    split1h(v.x, h0, l0); split1h(v.y, h1, l1);
    split1h(v.z, h2, l2); split1h(v.w, h3, l3);
    *(uint2*)(hi + i) = make_uint2(pack2h(h0, h1), pack2h(h2, h3));
    *(uint2*)(lo + i) = make_uint2(pack2h(l0, l1), pack2h(l2, l3));
}

__global__ void conv_f16_kernel(const float* __restrict__ src,
                                __half* __restrict__ dst, int n)
{
    int i = (blockIdx.x * blockDim.x + threadIdx.x) * 4;
    if (i >= n) return;
    float4 v = *(const float4*)(src + i);
    *(uint2*)(dst + i) = make_uint2(pack2h(__float2half(v.x), __float2half(v.y)),
                                    pack2h(__float2half(v.z), __float2half(v.w)));
}

// v slice of g_qkv (strided) -> contiguous fp16 hi/lo [MALL x HH]
__global__ void split_v16_kernel()
{
    int i = (blockIdx.x * blockDim.x + threadIdx.x) * 4;
    if (i >= MALL * HH) return;
    int r = i / HH, c = i % HH;
    float4 v = *(const float4*)(g_qkv + (size_t)r * H3 + 2 * HH + c);
    __half h0, h1, h2, h3, l0, l1, l2, l3;
    split1h(v.x, h0, l0); split1h(v.y, h1, l1);
    split1h(v.z, h2, l2); split1h(v.w, h3, l3);
    *(uint2*)(g_svh + i) = make_uint2(pack2h(h0, h1), pack2h(h2, h3));
    *(uint2*)(g_svl + i) = make_uint2(pack2h(l0, l1), pack2h(l2, l3));
}

// ============================================================================
// fused RoPE + convert: q -> fp16 single, k -> fp16 single
// ============================================================================
__global__ void rope_split_kernel()
{
    const int gw   = blockIdx.x * 8 + (threadIdx.x >> 5);
    const int lane = threadIdx.x & 31;
    const int h = gw & 15;
    const int s = (gw >> 4) & 2047;
    const int b = gw >> 15;

    const size_t qbase = (size_t)(b * SS + s) * H3 + h * HDIM;
    const int d0 = lane * 4;
    float4 q = *(const float4*)(g_qkv + qbase + d0);
    float4 k = *(const float4*)(g_qkv + qbase + HH + d0);

    float4 qp, kp;
    qp.x = __shfl_xor_sync(0xffffffffu, q.x, 4);
    qp.y = __shfl_xor_sync(0xffffffffu, q.y, 4);
    qp.z = __shfl_xor_sync(0xffffffffu, q.z, 4);
    qp.w = __shfl_xor_sync(0xffffffffu, q.w, 4);
    kp.x = __shfl_xor_sync(0xffffffffu, k.x, 4);
    kp.y = __shfl_xor_sync(0xffffffffu, k.y, 4);
    kp.z = __shfl_xor_sync(0xffffffffu, k.z, 4);
    kp.w = __shfl_xor_sync(0xffffffffu, k.w, 4);

    if (lane < 8) {
        const float sgn = (lane < 4) ? -1.0f : 1.0f;
        float qa[4] = {q.x, q.y, q.z, q.w};
        float pa[4] = {qp.x, qp.y, qp.z, qp.w};
        float ka[4] = {k.x, k.y, k.z, k.w};
        float kb[4] = {kp.x, kp.y, kp.z, kp.w};
#pragma unroll
        for (int i = 0; i < 4; i++) {
            int j = (lane & 3) * 4 + i;
            float inv = __expf(-(float)(2 * j) * (9.210340371976184f / 32.0f));
            float sn, cs;
            sincosf((float)s * inv, &sn, &cs);
            qa[i] = qa[i] * cs + sgn * pa[i] * sn;
            ka[i] = ka[i] * cs + sgn * kb[i] * sn;
        }
        q = make_float4(qa[0], qa[1], qa[2], qa[3]);
        k = make_float4(ka[0], ka[1], ka[2], ka[3]);
    }

    const size_t o = (size_t)(b * SS + s) * HH + h * HDIM + d0;
    *(uint2*)(g_q16 + o) = make_uint2(pack2h(__float2half(q.x), __float2half(q.y)),
                                      pack2h(__float2half(q.z), __float2half(q.w)));
    *(uint2*)(g_k16 + o) = make_uint2(pack2h(__float2half(k.x), __float2half(k.y)),
                                      pack2h(__float2half(k.z), __float2half(k.w)));
}

// ============================================================================
// Unified fp16 GEMM: C = (Ah [+ Al]) @ B^T + bias.
// NA: A terms. WN: warp N-width (16 -> BN=128, 32 -> BN=256).
// OUT: 0 = fp32 C, 1 = fp16 hi/lo (Chi, Clo), 2 = fp16 single (C16).
// ============================================================================
#define PADH     40
#define A_TILE_H (128 * PADH * 2)          // 10240 B

template <int NA, int WN, int OUT>
__global__ __launch_bounds__(512, 1) void gemm_f16_kernel(
    const __half* __restrict__ Ah, const __half* __restrict__ Al,
    const __half* __restrict__ Bw,
    const float* __restrict__ bias,
    float* __restrict__ C,
    __half* __restrict__ Chi, __half* __restrict__ Clo,
    __half* __restrict__ C16,
    int ldc, int N, int K)
{
    constexpr int BN     = WN * 8;
    constexpr int B_TILE = BN * PADH * 2;
    constexpr int STAGE  = NA * A_TILE_H + B_TILE;
    constexpr int NJ     = WN / 16;

    extern __shared__ char smem[];
    const uint32_t sbase = smem_u32(smem);
    const int t    = threadIdx.x;
    const int w    = t >> 5;
    const int lane = t & 31;
    const int wm   = w >> 3;
    const int wn   = w & 7;
    const int m0   = blockIdx.y * 128;
    const int n0   = blockIdx.x * BN;

    wmma::fragment<wmma::accumulator, 16, 16, 16, float> acc[4][NJ];
#pragma unroll
    for (int i = 0; i < 4; i++)
#pragma unroll
        for (int j = 0; j < NJ; j++) wmma::fill_fragment(acc[i][j], 0.0f);

    const int nchunks = K / 32;

    auto load_stage = [&](int chunk, int stage) {
        const int kk = chunk * 32;
        const uint32_t sst = sbase + stage * STAGE;
#pragma unroll
        for (int rep = 0; rep < NA; rep++) {
            const int v = t + rep * 512;
            const int tile = v >> 9;
            const int r = (v >> 2) & 127;
            const int c = (v & 3) * 8;
            const __half* src = tile ? Al : Ah;
            cp16(sst + tile * A_TILE_H + r * (PADH * 2) + c * 2,
                 src + (size_t)(m0 + r) * K + kk + c, 16);
        }
        constexpr int BREP = BN / 128;
#pragma unroll
        for (int rep = 0; rep < BREP; rep++) {
            const int v = t + rep * 512;
            const int r = v >> 2;
            const int c = (v & 3) * 8;
            const int brow = n0 + r;
            const uint32_t vb = (brow < N) ? 16u : 0u;
            cp16(sst + NA * A_TILE_H + r * (PADH * 2) + c * 2,
                 Bw + (size_t)(brow < N ? brow : 0) * K + kk + c, vb);
        }
        cp_commit();
    };

    load_stage(0, 0);

    for (int chunk = 0; chunk < nchunks; chunk++) {
        const int stage = chunk & 1;
        if (chunk + 1 < nchunks) { load_stage(chunk + 1, stage ^ 1); cp_wait<1>(); }
        else cp_wait<0>();
        __syncthreads();

        const __half* sAh = (const __half*)(smem + stage * STAGE);
        const __half* sAl = (const __half*)(smem + stage * STAGE + A_TILE_H);
        const __half* sB  = (const __half*)(smem + stage * STAGE + NA * A_TILE_H);

#pragma unroll
        for (int ks = 0; ks < 2; ks++) {
            wmma::fragment<wmma::matrix_b, 16, 16, 16, __half, wmma::col_major> bf[NJ];
#pragma unroll
            for (int j = 0; j < NJ; j++) {
                const int col = wn * WN + j * 16;
                wmma::load_matrix_sync(bf[j], sB + col * PADH + ks * 16, PADH);
            }
#pragma unroll
            for (int i = 0; i < 4; i++) {
                const int row = wm * 64 + i * 16;
                wmma::fragment<wmma::matrix_a, 16, 16, 16, __half, wmma::row_major> ah;
                wmma::load_matrix_sync(ah, sAh + row * PADH + ks * 16, PADH);
#pragma unroll
                for (int j = 0; j < NJ; j++)
                    wmma::mma_sync(acc[i][j], ah, bf[j], acc[i][j]);
                if (NA == 2) {
                    wmma::fragment<wmma::matrix_a, 16, 16, 16, __half, wmma::row_major> al;
                    wmma::load_matrix_sync(al, sAl + row * PADH + ks * 16, PADH);
#pragma unroll
                    for (int j = 0; j < NJ; j++)
                        wmma::mma_sync(acc[i][j], al, bf[j], acc[i][j]);
                }
            }
        }
        __syncthreads();
    }

    float* epi = (float*)(smem) + w * 256;
#pragma unroll
    for (int i = 0; i < 4; i++)
#pragma unroll
        for (int j = 0; j < NJ; j++) {
            const int gcol0 = n0 + wn * WN + j * 16;
            if (gcol0 < N) {
                wmma::store_matrix_sync(epi, acc[i][j], 16, wmma::mem_row_major);
                __syncwarp();
                const int row  = lane >> 1;
                const int coff = (lane & 1) * 8;
                const int grow = m0 + wm * 64 + i * 16 + row;
                const int gcol = gcol0 + coff;
                float4 b0 = *(const float4*)(bias + gcol);
                float4 b1 = *(const float4*)(bias + gcol + 4);
                const float* e = epi + row * 16 + coff;
                float vals[8] = {e[0] + b0.x, e[1] + b0.y, e[2] + b0.z, e[3] + b0.w,
                                 e[4] + b1.x, e[5] + b1.y, e[6] + b1.z, e[7] + b1.w};
                if (OUT == 0) {
                    float* cp = C + (size_t)grow * ldc + gcol;
                    *(float4*)cp       = make_float4(vals[0], vals[1], vals[2], vals[3]);
                    *(float4*)(cp + 4) = make_float4(vals[4], vals[5], vals[6], vals[7]);
                } else if (OUT == 1) {
                    __half hh[8], ll[8];
#pragma unroll
                    for (int c = 0; c < 8; c++) split1h(vals[c], hh[c], ll[c]);
                    *(uint4*)(Chi + (size_t)grow * ldc + gcol) = make_uint4(
                        pack2h(hh[0], hh[1]), pack2h(hh[2], hh[3]),
                        pack2h(hh[4], hh[5]), pack2h(hh[6], hh[7]));
                    *(uint4*)(Clo + (size_t)grow * ldc + gcol) = make_uint4(
                        pack2h(ll[0], ll[1]), pack2h(ll[2], ll[3]),
                        pack2h(ll[4], ll[5]), pack2h(ll[6], ll[7]));
                } else {
                    *(uint4*)(C16 + (size_t)grow * ldc + gcol) = make_uint4(
                        pack2h(__float2half(vals[0]), __float2half(vals[1])),
                        pack2h(__float2half(vals[2]), __float2half(vals[3])),
                        pack2h(__float2half(vals[4]), __float2half(vals[5])),
                        pack2h(__float2half(vals[6]), __float2half(vals[7])));
                }
                __syncwarp();
            }
        }
}

#define GEMM_SMEM_2_32 (2 * (2 * A_TILE_H + 256 * PADH * 2))   // 81920
#define GEMM_SMEM_2_16 (2 * (2 * A_TILE_H + 128 * PADH * 2))   // 61440

// ============================================================================
// fp16 flash attention (causal), single-term: Q, K, P, V all single fp16.
// Epilogue still writes att hi/lo (exact interface to Wd).
// ============================================================================
#define FQ_LD 136
#define FS_LD 68
#define FP_LD 72
#define FO_LD 132
#define QS_OFF 0
#define KS_OFF 17408
#define VS_OFF 34816
#define S_OFF  52224
#define PS_OFF 69632
#define OT_OFF 78848
#define FLASH_SMEM 112640

__global__ __launch_bounds__(256, 1) void flash_kernel()
{
    extern __shared__ char sm[];
    const uint32_t sb = smem_u32(sm);
    __half* Qs = (__half*)(sm + QS_OFF);
    __half* Ks = (__half*)(sm + KS_OFF);
    __half* Vs = (__half*)(sm + VS_OFF);
    float*  Ss = (float*)(sm + S_OFF);
    __half* Ps = (__half*)(sm + PS_OFF);
    float*  Ot = (float*)(sm + OT_OFF);

    const int qt = gridDim.x - 1 - blockIdx.x;   // heavy tiles first
    const int h  = blockIdx.y;
    const int b  = blockIdx.z;
    const int q0 = qt * 64;
    const int t  = threadIdx.x;
    const int tx = t & 15;
    const int ty = t >> 4;
    const int w  = t >> 5;
    const int wr = w >> 1;
    const int wc = w & 1;

    for (int i = t; i < 1024; i += 256) {
        const int r = i >> 4;
        const int c = (i & 15) << 3;
        const size_t g = (size_t)(b * SS + q0 + r) * HH + h * HDIM + c;
        cp16(sb + QS_OFF + (uint32_t)((r * FQ_LD + c) * 2), g_q16 + g, 16);
    }
    cp_commit();

    float m_i[4], l_i[4], O[4][8];
#pragma unroll
    for (int i = 0; i < 4; i++) {
        m_i[i] = -1e30f; l_i[i] = 0.0f;
#pragma unroll
        for (int c = 0; c < 8; c++) O[i][c] = 0.0f;
    }
    const float scale = 0.08838834764831843f;

    for (int kt = 0; kt <= qt; kt++) {
        const int k0 = kt * 64;
        for (int i = t; i < 1024; i += 256) {
            const int r = i >> 4;
            const int c = (i & 15) << 3;
            const size_t g = (size_t)(b * SS + k0 + r) * HH + h * HDIM + c;
            cp16(sb + KS_OFF + (uint32_t)((r * FQ_LD + c) * 2), g_k16 + g, 16);
        }
        cp_commit();
        for (int i = t; i < 1024; i += 256) {
            const int r = i >> 4;
            const int c = (i & 15) << 3;
            const size_t g = (size_t)(b * SS + k0 + r) * HH + h * HDIM + c;
            cp16(sb + VS_OFF + (uint32_t)((r * FQ_LD + c) * 2), g_v16 + g, 16);
        }
        cp_commit();
        cp_wait<1>();
        __syncthreads();

        // ---- S = Q K^T (1 term) ----
        {
            wmma::fragment<wmma::accumulator, 16, 16, 16, float> sacc[2];
            wmma::fill_fragment(sacc[0], 0.0f);
            wmma::fill_fragment(sacc[1], 0.0f);
#pragma unroll
            for (int k = 0; k < 8; k++) {
                wmma::fragment<wmma::matrix_a, 16, 16, 16, __half, wmma::row_major> af;
                wmma::load_matrix_sync(af, Qs + (wr * 16) * FQ_LD + k * 16, FQ_LD);
#pragma unroll
                for (int jj = 0; jj < 2; jj++) {
                    const int col0 = wc * 32 + jj * 16;
                    wmma::fragment<wmma::matrix_b, 16, 16, 16, __half, wmma::col_major> bf;
                    wmma::load_matrix_sync(bf, Ks + col0 * FQ_LD + k * 16, FQ_LD);
                    wmma::mma_sync(sacc[jj], af, bf, sacc[jj]);
                }
            }
#pragma unroll
            for (int jj = 0; jj < 2; jj++)
                wmma::store_matrix_sync(&Ss[(wr * 16) * FS_LD + wc * 32 + jj * 16],
                                        sacc[jj], FS_LD, wmma::mem_row_major);
        }
        __syncthreads();

        // ---- online softmax ----
        float corr[4];
#pragma unroll
        for (int i = 0; i < 4; i++) {
            const int row = ty * 4 + i;
            const int qg  = q0 + row;
            float sv[4], rmax = -1e30f;
#pragma unroll
            for (int j = 0; j < 4; j++) {
                float s = Ss[row * FS_LD + tx + 16 * j] * scale;
                if (k0 + tx + 16 * j > qg) s = -1e30f;
                sv[j] = s;
                rmax = fmaxf(rmax, s);
            }
#pragma unroll
            for (int off = 8; off >= 1; off >>= 1)
                rmax = fmaxf(rmax, __shfl_xor_sync(0xffffffffu, rmax, off));
            const float mnew = fmaxf(m_i[i], rmax);
            corr[i] = __expf(m_i[i] - mnew);
            float rsum = 0.0f;
#pragma unroll
            for (int j = 0; j < 4; j++) {
                const float p = __expf(sv[j] - mnew);
                Ps[row * FP_LD + tx + 16 * j] = __float2half(p);
                rsum += p;
            }
#pragma unroll
            for (int off = 8; off >= 1; off >>= 1)
                rsum += __shfl_xor_sync(0xffffffffu, rsum, off);
            l_i[i] = l_i[i] * corr[i] + rsum;
            m_i[i] = mnew;
        }
        cp_wait<0>();
        __syncthreads();

        // ---- Otmp = P V (1 term) ----
        {
            wmma::fragment<wmma::accumulator, 16, 16, 16, float> oacc[4];
#pragma unroll
            for (int jj = 0; jj < 4; jj++) wmma::fill_fragment(oacc[jj], 0.0f);
#pragma unroll
            for (int k = 0; k < 4; k++) {
                wmma::fragment<wmma::matrix_a, 16, 16, 16, __half, wmma::row_major> pf;
                wmma::load_matrix_sync(pf, Ps + (wr * 16) * FP_LD + k * 16, FP_LD);
#pragma unroll
                for (int jj = 0; jj < 4; jj++) {
                    const int col0 = wc * 64 + jj * 16;
                    wmma::fragment<wmma::matrix_b, 16, 16, 16, __half, wmma::row_major> vb;
                    wmma::load_matrix_sync(vb, Vs + (k * 16) * FQ_LD + col0, FQ_LD);
                    wmma::mma_sync(oacc[jj], pf, vb, oacc[jj]);
                }
            }
#pragma unroll
            for (int jj = 0; jj < 4; jj++)
                wmma::store_matrix_sync(&Ot[(wr * 16) * FO_LD + wc * 64 + jj * 16],
                                        oacc[jj], FO_LD, wmma::mem_row_major);
        }
        __syncthreads();

#pragma unroll
        for (int i = 0; i < 4; i++) {
            const int row = ty * 4 + i;
#pragma unroll
            for (int c = 0; c < 8; c++)
                O[i][c] = O[i][c] * corr[i] + Ot[row * FO_LD + tx * 8 + c];
        }
    }

    // epilogue: fp16 hi/lo att (exact interface to 2-term Wd GEMM)
#pragma unroll
    for (int i = 0; i < 4; i++) {
        const float inv = 1.0f / l_i[i];
        const int qg = q0 + ty * 4 + i;
        const size_t o = (size_t)(b * SS + qg) * HH + h * HDIM + tx * 8;
        __half hh[8], ll[8];
#pragma unroll
        for (int c = 0; c < 8; c++) split1h(O[i][c] * inv, hh[c], ll[c]);
        *(uint4*)(g_ah16 + o) = make_uint4(pack2h(hh[0], hh[1]), pack2h(hh[2], hh[3]),
                                           pack2h(hh[4], hh[5]), pack2h(hh[6], hh[7]));
        *(uint4*)(g_al16 + o) = make_uint4(pack2h(ll[0], ll[1]), pack2h(ll[2], ll[3]),
                                           pack2h(ll[4], ll[5]), pack2h(ll[6], ll[7]));
    }
}

// ============================================================================
// Launch
// ============================================================================
extern "C" void kernel_launch(void* const* d_in, const int* in_sizes, int n_in,
                              void* d_out, int out_size)
{
    const float* x    = (const float*)d_in[0];
    const float* Wqkv = (const float*)d_in[1];
    const float* bqkv = (const float*)d_in[2];
    const float* Wc   = (const float*)d_in[3];
    const float* bc   = (const float*)d_in[4];
    const float* Wr   = (const float*)d_in[5];
    const float* br   = (const float*)d_in[6];
    const float* Wd   = (const float*)d_in[7];
    const float* bd   = (const float*)d_in[8];
    float* out = (float*)d_out;

    float* qkv;
    cudaGetSymbolAddress((void**)&qkv, g_qkv);
    __half *xh16, *xl16, *wq16, *wd16, *wc16, *wr16,
           *svh, *svl, *vch16, *vcl16, *ah16, *al16, *v16;
    cudaGetSymbolAddress((void**)&xh16,  g_xh16);
    cudaGetSymbolAddress((void**)&xl16,  g_xl16);
    cudaGetSymbolAddress((void**)&wq16,  g_wq16);
    cudaGetSymbolAddress((void**)&wd16,  g_wd16);
    cudaGetSymbolAddress((void**)&wc16,  g_wc16);
    cudaGetSymbolAddress((void**)&wr16,  g_wr16);
    cudaGetSymbolAddress((void**)&svh,   g_svh);
    cudaGetSymbolAddress((void**)&svl,   g_svl);
    cudaGetSymbolAddress((void**)&vch16, g_vch16);
    cudaGetSymbolAddress((void**)&vcl16, g_vcl16);
    cudaGetSymbolAddress((void**)&ah16,  g_ah16);
    cudaGetSymbolAddress((void**)&al16,  g_al16);
    cudaGetSymbolAddress((void**)&v16,   g_v16);

    cudaFuncSetAttribute((const void*)gemm_f16_kernel<2, 32, 0>,
                         cudaFuncAttributeMaxDynamicSharedMemorySize, GEMM_SMEM_2_32);
    cudaFuncSetAttribute((const void*)gemm_f16_kernel<2, 16, 1>,
                         cudaFuncAttributeMaxDynamicSharedMemorySize, GEMM_SMEM_2_16);
    cudaFuncSetAttribute((const void*)gemm_f16_kernel<2, 32, 2>,
                         cudaFuncAttributeMaxDynamicSharedMemorySize, GEMM_SMEM_2_32);
    cudaFuncSetAttribute((const void*)flash_kernel,
                         cudaFuncAttributeMaxDynamicSharedMemorySize, FLASH_SMEM);

    // #1-#5: conversions
    split_f16_kernel<<<(MALL * HH / 4 + 255) / 256, 256>>>(x, xh16, xl16, MALL * HH);
    conv_f16_kernel<<<(H3 * HH / 4 + 255) / 256, 256>>>(Wqkv, wq16, H3 * HH);
    conv_f16_kernel<<<(VP * HH / 4 + 255) / 256, 256>>>(Wc, wc16, VP * HH);
    conv_f16_kernel<<<(HH * VP / 4 + 255) / 256, 256>>>(Wr, wr16, HH * VP);
    conv_f16_kernel<<<(HH * HH / 4 + 255) / 256, 256>>>(Wd, wd16, HH * HH);

    // #6: qkv = x @ Wqkv^T + bqkv (2-term fp16 -> fp32)
    gemm_f16_kernel<2, 32, 0><<<dim3(H3 / 256, MALL / 128), 512, GEMM_SMEM_2_32>>>(
        xh16, xl16, wq16, bqkv, qkv, nullptr, nullptr, nullptr, H3, H3, HH);

    // #7: fused RoPE -> q fp16, k fp16
    rope_split_kernel<<<BB * SS * NHEAD / 8, 256>>>();

    // #8: v slice -> fp16 hi/lo
    split_v16_kernel<<<(MALL * HH / 4 + 255) / 256, 256>>>();

    // #9: vc = v @ Wc^T + bc (2-term fp16 -> fp16 hi/lo), N=320, BN=128
    gemm_f16_kernel<2, 16, 1><<<dim3((VP + 127) / 128, MALL / 128), 512, GEMM_SMEM_2_16>>>(
        svh, svl, wc16, bc, nullptr, vch16, vcl16, nullptr, VP, VP, HH);

    // #10: vr = vc @ Wr^T + br (2-term fp16 -> fp16 single), K=320
    gemm_f16_kernel<2, 32, 2><<<dim3(HH / 256, MALL / 128), 512, GEMM_SMEM_2_32>>>(
        vch16, vcl16, wr16, br, nullptr, nullptr, nullptr, v16, HH, HH, VP);

    // #11: flash attention (single-term fp16) -> fp16 hi/lo att
    flash_kernel<<<dim3(SS / 64, NHEAD, BB), 256, FLASH_SMEM>>>();

    // #12: out = att @ Wd^T + bd (2-term fp16 -> fp32)
    gemm_f16_kernel<2, 32, 0><<<dim3(HH / 256, MALL / 128), 512, GEMM_SMEM_2_32>>>(
        ah16, al16, wd16, bd, out, nullptr, nullptr, nullptr, HH, HH, HH);
}